// round 11
// baseline (speedup 1.0000x reference)
#include <cuda_runtime.h>
#include <cuda_fp16.h>
#include <cstdint>
#include <math.h>

#define Bsz 32
#define Tsz 512
#define DIsz 512
#define Hsz 512
#define G4 2048
#define G5 2560
#define NCTA 148
#define NTHR 512
#define BTHn ((size_t)32*512*512)

typedef unsigned int uint;
typedef unsigned short ushort;

// ---- static device scratch ----
// h stored as ONE fp16, layout [layer][t][b][k]; c fp32 [layer][t][b][j]
static __device__ __align__(16) ushort g_hh[(size_t)4*512*32*512];
static __device__ float g_c[(size_t)4*512*32*512];
static __device__ float g_xt[(size_t)512*2048*32];           // [t][rowp][b]
// single-fp16 weights in mma A-fragment order, one region per (block, m-tile)
static __device__ __align__(16) uint g_wA0[(size_t)16*8*32*128];     // L0: [cta][mw8][ks32][lane*4+reg]
static __device__ __align__(16) uint g_wAca[(size_t)132*4*64*128];   // CA: [lc][mw4][ks64][lane*4+reg]
static __device__ unsigned g_done[4];                        // per-layer step counters

#define PART_OFF 66048       // bytes: B region = 32*1032 ushorts * 2B (max, CA)

// fast activations (MUFU-based, ~1e-7 error, correct saturation)
__device__ __forceinline__ float sigf(float x) {
    return __fdividef(1.0f, 1.0f + __expf(-x));
}
__device__ __forceinline__ float tanhef(float x) {
    return __fdividef(2.0f, 1.0f + __expf(-2.0f * x)) - 1.0f;
}

__device__ __forceinline__ ushort f16of(float w) {
    return __half_as_ushort(__float2half_rn(w));
}

__device__ __forceinline__ void mma_f16(float* d, const uint4& a, uint b0, uint b1) {
    asm volatile(
        "mma.sync.aligned.m16n8k16.row.col.f32.f16.f16.f32 "
        "{%0,%1,%2,%3},{%4,%5,%6,%7},{%8,%9},{%0,%1,%2,%3};"
        : "+f"(d[0]), "+f"(d[1]), "+f"(d[2]), "+f"(d[3])
        : "r"(a.x), "r"(a.y), "r"(a.z), "r"(a.w), "r"(b0), "r"(b1));
}

static __device__ __host__ __forceinline__ void cta_params(int ci, int& nj, int& j0) {
    if (ci < 28) { nj = 12; j0 = ci * 12; }
    else         { nj = 11; j0 = 336 + (ci - 28) * 11; }
}

// ---------------- weight fragment packing + counter reset ----------------
__global__ void __launch_bounds__(256) k_fill(const float* __restrict__ w_hh,
                                              const float* __restrict__ ca_w)
{
    size_t stride = (size_t)gridDim.x * blockDim.x;
    size_t i0 = (size_t)blockIdx.x * blockDim.x + threadIdx.x;
    if (i0 < 4) g_done[i0] = 0u;

    // L0: e = ((cta*8 + mw)*32 + ks)*128 + lane*4 + reg ; full K=512 per region
    const size_t N0 = (size_t)16*8*32*128;
    for (size_t e = i0; e < N0; e += stride) {
        int reg = (int)(e & 3), lane = (int)((e >> 2) & 31), ks = (int)((e >> 7) & 31);
        int mw = (int)((e >> 12) & 7), cta = (int)(e >> 15);
        int gr = lane >> 2, c0 = (lane & 3) * 2;
        int slot = mw * 16 + gr + (reg & 1) * 8;                 // 0..127
        int kk = ks * 16 + c0 + ((reg >> 1) & 1) * 8;            // 0..511
        int row = (slot >> 5) * 512 + cta * 32 + (slot & 31);
        float w0 = w_hh[(size_t)row * 512 + kk];
        float w1 = w_hh[(size_t)row * 512 + kk + 1];
        g_wA0[e] = (uint)f16of(w0) | ((uint)f16of(w1) << 16);
    }
    // CA: e = ((lc*4 + mw)*64 + ks)*128 + lane*4 + reg ; full K=1024 per region
    const size_t NC = (size_t)132*4*64*128;
    for (size_t e = i0; e < NC; e += stride) {
        int reg = (int)(e & 3), lane = (int)((e >> 2) & 31), ks = (int)((e >> 7) & 63);
        int mw = (int)((e >> 13) & 3), lc = (int)(e >> 15);
        int gr = lane >> 2, c0 = (lane & 3) * 2;
        int slot = mw * 16 + gr + (reg & 1) * 8;                 // 0..63
        int kk = ks * 16 + c0 + ((reg >> 1) & 1) * 8;            // 0..1023
        int ci = lc % 44, l = lc / 44;
        int nj, j0; cta_params(ci, nj, j0);
        float w0 = 0.0f, w1 = 0.0f;
        if (slot < 5 * nj) {
            int g = slot / nj, jj = slot - g * nj;
            int row = g * 512 + j0 + jj;
            w0 = ca_w[((size_t)l * G5 + row) * 1024 + kk];
            w1 = ca_w[((size_t)l * G5 + row) * 1024 + kk + 1];
        }
        g_wAca[e] = (uint)f16of(w0) | ((uint)f16of(w1) << 16);
    }
}

// ---------------- xproj = x @ w_ih.T + bias, stored [t][rowp][b] ----------------
__global__ void __launch_bounds__(256) k_xproj(
    const float* __restrict__ x, const float* __restrict__ w_ih,
    const float* __restrict__ b_ih, const float* __restrict__ b_hh)
{
    __shared__ float As[16][65];
    __shared__ float Bs[16][65];
    const int bm = blockIdx.y * 64, bn = blockIdx.x * 64;
    const int tid = threadIdx.x;
    const int tr = (tid >> 4) << 2, tc = (tid & 15) << 2;
    float acc[4][4] = {};
    for (int k0 = 0; k0 < DIsz; k0 += 16) {
        #pragma unroll
        for (int i0 = 0; i0 < 4; i0++) {
            int i = i0 * 256 + tid;
            int mm = i >> 4, kk = i & 15;
            int m = bm + mm, tt = m >> 5, bb = m & 31;
            As[kk][mm] = x[((size_t)bb * Tsz + tt) * DIsz + (k0 + kk)];
            Bs[kk][mm] = w_ih[(size_t)(bn + mm) * DIsz + (k0 + kk)];
        }
        __syncthreads();
        #pragma unroll
        for (int kk = 0; kk < 16; kk++) {
            float a[4] = {As[kk][tr], As[kk][tr+1], As[kk][tr+2], As[kk][tr+3]};
            float b[4] = {Bs[kk][tc], Bs[kk][tc+1], Bs[kk][tc+2], Bs[kk][tc+3]};
            #pragma unroll
            for (int i = 0; i < 4; i++)
                #pragma unroll
                for (int j = 0; j < 4; j++)
                    acc[i][j] = fmaf(a[i], b[j], acc[i][j]);
        }
        __syncthreads();
    }
    #pragma unroll
    for (int i = 0; i < 4; i++) {
        int m = bm + tr + i, tt = m >> 5, bb = m & 31;
        #pragma unroll
        for (int j = 0; j < 4; j++) {
            int n = bn + tc + j;
            int g = n >> 9, cd = (n >> 5) & 15, jj = n & 31;
            g_xt[((size_t)tt * 2048 + cd * 128 + g * 32 + jj) * 32 + bb]
                = acc[i][j] + b_ih[n] + b_hh[n];
        }
    }
}

// ---------------- persistent self-timed LSTM, full-K warps, no reduce ----------------
__global__ void __launch_bounds__(NTHR, 1) k_wave(
    const float* __restrict__ ca_b, float* __restrict__ out)
{
    extern __shared__ char smx[];

    const int tid  = threadIdx.x;
    const int lane = tid & 31;
    const int wid  = tid >> 5;
    const int cta  = blockIdx.x;
    const int gr = lane >> 2, c0 = (lane & 3) * 2;

    int layer, j0, nj, ci = 0;
    if (cta < 16) { layer = 0; nj = 32; j0 = cta * 32; }
    else {
        int r = cta - 16;
        layer = 1 + r / 44;
        ci = r % 44;
        cta_params(ci, nj, j0);
    }
    const int K  = (layer == 0) ? 512 : 1024;
    const int rs = K + 8;
    ushort* Bh = (ushort*)smx;
    float* part = (float*)(smx + PART_OFF);   // 128*33 floats

    // warp roles + weight region + constant bias accumulator seeds (CA)
    int mw, np = 0;
    const uint4* wp4;
    float bias0 = 0.0f, bias1 = 0.0f;
    if (layer == 0) {
        mw = wid >> 1; np = wid & 1;
        wp4 = (const uint4*)g_wA0 + ((size_t)(cta * 8 + mw)) * 1024 + lane;
    } else {
        mw = wid >> 2; np = wid & 3;     // np = nt (0..3)
        wp4 = (const uint4*)g_wAca + ((size_t)(((layer - 1) * 44 + ci) * 4 + mw)) * 2048 + lane;
        const float* cb = ca_b + (size_t)(layer - 1) * G5;
        int s0 = mw * 16 + gr, s1 = s0 + 8;
        if (s0 < 5 * nj) bias0 = cb[(s0 / nj) * 512 + j0 + (s0 % nj)];
        if (s1 < 5 * nj) bias1 = cb[(s1 / nj) * 512 + j0 + (s1 % nj)];
    }

    for (int t = 0; t < Tsz; ++t) {
        if (layer == 0) {
            // ---- wait own-layer, stage, GEMM ----
            if (tid == 0 && t > 0) {
                volatile unsigned* p = &g_done[0];
                while (*p < 16u * (unsigned)t) { }
                __threadfence();
            }
            __syncthreads();
            {
                const uint4 zz = make_uint4(0, 0, 0, 0);
                for (int e = tid; e < 32 * 64; e += NTHR) {
                    int b = e >> 6, c = e & 63;
                    int k8 = c * 8;
                    uint4 vh = (t > 0)
                        ? __ldcg((const uint4*)(g_hh + (((size_t)(t - 1)) * 32 + b) * 512 + k8))
                        : zz;
                    *(uint4*)(Bh + b * rs + k8) = vh;
                }
            }
            __syncthreads();
            {
                // accumulators seeded from xproj
                const float* xb = g_xt + ((size_t)t * 2048 + cta * 128) * 32;
                float d[2][4];
                int sl0 = mw * 16 + gr;
                #pragma unroll
                for (int ntp = 0; ntp < 2; ntp++) {
                    int bc = (np * 2 + ntp) * 8 + c0;
                    d[ntp][0] = __ldcg(xb + sl0 * 32 + bc);
                    d[ntp][1] = __ldcg(xb + sl0 * 32 + bc + 1);
                    d[ntp][2] = __ldcg(xb + (sl0 + 8) * 32 + bc);
                    d[ntp][3] = __ldcg(xb + (sl0 + 8) * 32 + bc + 1);
                }
                if (t > 0) {
                    uint4 ah = __ldg(wp4);
                    #pragma unroll 8
                    for (int ks = 0; ks < 32; ks++) {
                        uint4 nx = ah;
                        if (ks < 31) nx = __ldg(wp4 + (ks + 1) * 32);
                        int k = ks * 16 + c0;
                        #pragma unroll
                        for (int ntp = 0; ntp < 2; ntp++) {
                            const ushort* ph = Bh + ((np * 2 + ntp) * 8 + gr) * rs + k;
                            uint b0 = *(const uint*)ph, b1 = *(const uint*)(ph + 8);
                            mma_f16(d[ntp], ah, b0, b1);
                        }
                        ah = nx;
                    }
                }
                #pragma unroll
                for (int ntp = 0; ntp < 2; ntp++) {
                    int bc = (np * 2 + ntp) * 8 + c0;
                    part[sl0 * 33 + bc]           = d[ntp][0];
                    part[sl0 * 33 + bc + 1]       = d[ntp][1];
                    part[(sl0 + 8) * 33 + bc]     = d[ntp][2];
                    part[(sl0 + 8) * 33 + bc + 1] = d[ntp][3];
                }
            }
        } else {
            // ---- wait lower, stage low half ----
            if (tid == 0) {
                unsigned needl = (layer == 1 ? 16u : 44u) * (unsigned)(t + 1);
                volatile unsigned* pl = &g_done[layer - 1];
                while (*pl < needl) { }
                __threadfence();
            }
            __syncthreads();
            for (int e = tid; e < 32 * 64; e += NTHR) {
                int b = e >> 6, c = e & 63;
                int k8 = c * 8;
                uint4 vh = __ldcg((const uint4*)(
                    g_hh + (((size_t)(layer - 1) * Tsz + t) * 32 + b) * 512 + k8));
                *(uint4*)(Bh + b * rs + k8) = vh;
            }
            // ---- wait own layer, stage high half ----
            if (tid == 0 && t > 0) {
                volatile unsigned* po = &g_done[layer];
                while (*po < 44u * (unsigned)t) { }
                __threadfence();
            }
            __syncthreads();
            {
                const uint4 zz = make_uint4(0, 0, 0, 0);
                for (int e = tid; e < 32 * 64; e += NTHR) {
                    int b = e >> 6, c = e & 63;
                    int k8 = c * 8;
                    uint4 vh = (t > 0)
                        ? __ldcg((const uint4*)(
                              g_hh + (((size_t)layer * Tsz + (t - 1)) * 32 + b) * 512 + k8))
                        : zz;
                    *(uint4*)(Bh + b * rs + 512 + k8) = vh;
                }
            }
            __syncthreads();
            // ---- GEMM: one m16n8 tile per warp, full K ----
            {
                float d[4] = {bias0, bias0, bias1, bias1};
                uint4 ah = __ldg(wp4);
                #pragma unroll 8
                for (int ks = 0; ks < 64; ks++) {
                    uint4 nx = ah;
                    if (ks < 63) nx = __ldg(wp4 + (ks + 1) * 32);
                    int k = ks * 16 + c0;
                    const ushort* ph = Bh + (np * 8 + gr) * rs + k;
                    uint b0 = *(const uint*)ph, b1 = *(const uint*)(ph + 8);
                    mma_f16(d, ah, b0, b1);
                    ah = nx;
                }
                int sl0 = mw * 16 + gr;
                int bc = np * 8 + c0;
                part[sl0 * 33 + bc]           = d[0];
                part[sl0 * 33 + bc + 1]       = d[1];
                part[(sl0 + 8) * 33 + bc]     = d[2];
                part[(sl0 + 8) * 33 + bc + 1] = d[3];
            }
        }
        __syncthreads();

        // ---- activation + state update (part holds final gate pre-activations) ----
        {
            size_t so = (((size_t)layer * Tsz + t)) * 32;
            float*  cout = g_c  + so * 512;
            ushort* hho  = g_hh + so * 512;
            const float* cprev = (t > 0) ? g_c + (((size_t)layer * Tsz + (t - 1)) * 32) * 512 : nullptr;
            if (layer == 0) {
                for (int it = tid; it < 1024; it += NTHR) {
                    int b = it >> 5, jj = it & 31;
                    int j = cta * 32 + jj;
                    float i_ = part[(0 * 32 + jj) * 33 + b];
                    float f_ = part[(1 * 32 + jj) * 33 + b];
                    float gg = part[(2 * 32 + jj) * 33 + b];
                    float o_ = part[(3 * 32 + jj) * 33 + b];
                    float cp = cprev ? __ldcg(cprev + (size_t)b * 512 + j) : 0.0f;
                    float cv = sigf(i_) * tanhef(gg) + sigf(f_) * cp;
                    float hv = sigf(o_) * tanhef(cv);
                    cout[(size_t)b * 512 + j] = cv;
                    hho[(size_t)b * 512 + j]  = f16of(hv);
                }
            } else {
                const float* clow = g_c + (((size_t)(layer - 1) * Tsz + t) * 32) * 512;
                for (int it = tid; it < nj * 32; it += NTHR) {
                    int b = it / nj, jj = it - b * nj;
                    int j = j0 + jj;
                    float i_ = part[(0 * nj + jj) * 33 + b];
                    float fp = part[(1 * nj + jj) * 33 + b];
                    float fl = part[(2 * nj + jj) * 33 + b];
                    float u_ = part[(3 * nj + jj) * 33 + b];
                    float o_ = part[(4 * nj + jj) * 33 + b];
                    float cp = cprev ? __ldcg(cprev + (size_t)b * 512 + j) : 0.0f;
                    float cl = __ldcg(clow + (size_t)b * 512 + j);
                    float cv = cp * sigf(fp + 1.0f) + cl * sigf(fl + 1.0f) + tanhef(u_) * sigf(i_);
                    float hv = sigf(o_) * tanhef(cv);
                    cout[(size_t)b * 512 + j] = cv;
                    hho[(size_t)b * 512 + j]  = f16of(hv);
                    if (layer == 3) {
                        out[(size_t)b * Tsz * Hsz + (size_t)t * Hsz + j] = hv;
                        out[BTHn + (size_t)b * Tsz * Hsz + (size_t)t * Hsz + j] = cv;
                        if (t == Tsz - 1) {
                            out[2 * BTHn + (size_t)b * Hsz + j] = hv;
                            out[2 * BTHn + (size_t)Bsz * Hsz + (size_t)b * Hsz + j] = cv;
                        }
                    }
                }
            }
        }
        __syncthreads();

        // ---- publish completion of step t ----
        if (tid == 0) {
            __threadfence();
            atomicAdd(&g_done[layer], 1u);
        }
    }
}

extern "C" void kernel_launch(void* const* d_in, const int* in_sizes, int n_in,
                              void* d_out, int out_size)
{
    const float* x    = (const float*)d_in[0];
    const float* w_ih = (const float*)d_in[1];
    const float* w_hh = (const float*)d_in[2];
    const float* b_ih = (const float*)d_in[3];
    const float* b_hh = (const float*)d_in[4];
    const float* ca_w = (const float*)d_in[5];
    const float* ca_b = (const float*)d_in[6];
    float* out = (float*)d_out;
    (void)in_sizes; (void)n_in; (void)out_size;

    k_fill<<<296, 256>>>(w_hh, ca_w);

    dim3 g(G4 / 64, (Tsz * Bsz) / 64);
    k_xproj<<<g, 256>>>(x, w_ih, b_ih, b_hh);

    const int smem_bytes = PART_OFF + 128 * 33 * 4;  // 66048 + 16896 = 82944
    cudaFuncSetAttribute(k_wave, cudaFuncAttributeMaxDynamicSharedMemorySize, smem_bytes);
    k_wave<<<NCTA, NTHR, smem_bytes>>>(ca_b, out);
}

// round 12
// speedup vs baseline: 1.1461x; 1.1461x over previous
#include <cuda_runtime.h>
#include <cuda_fp16.h>
#include <cstdint>
#include <math.h>

#define Bsz 32
#define Tsz 512
#define DIsz 512
#define Hsz 512
#define G4 2048
#define G5 2560
#define NCTA 148
#define NTHR 512
#define BTHn ((size_t)32*512*512)

typedef unsigned int uint;
typedef unsigned short ushort;

// ---- static device scratch ----
// h stored as ONE fp16, layout [layer][t][b][k]; c fp32 [layer][t][b][j]
static __device__ __align__(16) ushort g_hh[(size_t)4*512*32*512];
static __device__ float g_c[(size_t)4*512*32*512];
static __device__ float g_xt[(size_t)512*2048*32];           // [t][rowp][b]
// single-fp16 weights in mma A-fragment order
static __device__ __align__(16) uint g_wA0[(size_t)16*8*32*128];     // L0: [cta][mw8][ks32][lane*4+reg]
static __device__ __align__(16) uint g_wAca[(size_t)132*8*32*128];   // CA: [lc][mw*2+kw][ks32][...]
static __device__ unsigned g_done[4];                        // per-layer step counters

#define PSTR 4224            // 128*33 floats per partial region
#define PART_OFF 66048       // bytes: B region = 32*1032 ushorts * 2B

// fast activations (MUFU-based, ~1e-7 error, correct saturation)
__device__ __forceinline__ float sigf(float x) {
    return __fdividef(1.0f, 1.0f + __expf(-x));
}
__device__ __forceinline__ float tanhef(float x) {
    return __fdividef(2.0f, 1.0f + __expf(-2.0f * x)) - 1.0f;
}

__device__ __forceinline__ ushort f16of(float w) {
    return __half_as_ushort(__float2half_rn(w));
}

__device__ __forceinline__ void mma_f16(float* d, const uint4& a, uint b0, uint b1) {
    asm volatile(
        "mma.sync.aligned.m16n8k16.row.col.f32.f16.f16.f32 "
        "{%0,%1,%2,%3},{%4,%5,%6,%7},{%8,%9},{%0,%1,%2,%3};"
        : "+f"(d[0]), "+f"(d[1]), "+f"(d[2]), "+f"(d[3])
        : "r"(a.x), "r"(a.y), "r"(a.z), "r"(a.w), "r"(b0), "r"(b1));
}

static __device__ __host__ __forceinline__ void cta_params(int ci, int& nj, int& j0) {
    if (ci < 28) { nj = 12; j0 = ci * 12; }
    else         { nj = 11; j0 = 336 + (ci - 28) * 11; }
}

// ---------------- weight fragment packing + counter reset ----------------
__global__ void __launch_bounds__(256) k_fill(const float* __restrict__ w_hh,
                                              const float* __restrict__ ca_w)
{
    size_t stride = (size_t)gridDim.x * blockDim.x;
    size_t i0 = (size_t)blockIdx.x * blockDim.x + threadIdx.x;
    if (i0 < 4) g_done[i0] = 0u;

    // L0: e = ((cta*8 + mw)*32 + ks)*128 + lane*4 + reg ; full K=512 per region
    const size_t N0 = (size_t)16*8*32*128;
    for (size_t e = i0; e < N0; e += stride) {
        int reg = (int)(e & 3), lane = (int)((e >> 2) & 31), ks = (int)((e >> 7) & 31);
        int mw = (int)((e >> 12) & 7), cta = (int)(e >> 15);
        int gr = lane >> 2, c0 = (lane & 3) * 2;
        int slot = mw * 16 + gr + (reg & 1) * 8;                 // 0..127
        int kk = ks * 16 + c0 + ((reg >> 1) & 1) * 8;            // 0..511
        int row = (slot >> 5) * 512 + cta * 32 + (slot & 31);
        float w0 = w_hh[(size_t)row * 512 + kk];
        float w1 = w_hh[(size_t)row * 512 + kk + 1];
        g_wA0[e] = (uint)f16of(w0) | ((uint)f16of(w1) << 16);
    }
    // CA: e = ((lc*8 + mw*2+kw)*32 + ks)*128 + lane*4 + reg ; K half (512) per region
    const size_t NC = (size_t)132*8*32*128;
    for (size_t e = i0; e < NC; e += stride) {
        int reg = (int)(e & 3), lane = (int)((e >> 2) & 31), ks = (int)((e >> 7) & 31);
        int mk = (int)((e >> 12) & 7), lc = (int)(e >> 15);
        int mw = mk >> 1, kw = mk & 1;
        int gr = lane >> 2, c0 = (lane & 3) * 2;
        int slot = mw * 16 + gr + (reg & 1) * 8;                 // 0..63
        int kk = kw * 512 + ks * 16 + c0 + ((reg >> 1) & 1) * 8; // 0..1023
        int ci = lc % 44, l = lc / 44;
        int nj, j0; cta_params(ci, nj, j0);
        float w0 = 0.0f, w1 = 0.0f;
        if (slot < 5 * nj) {
            int g = slot / nj, jj = slot - g * nj;
            int row = g * 512 + j0 + jj;
            w0 = ca_w[((size_t)l * G5 + row) * 1024 + kk];
            w1 = ca_w[((size_t)l * G5 + row) * 1024 + kk + 1];
        }
        g_wAca[e] = (uint)f16of(w0) | ((uint)f16of(w1) << 16);
    }
}

// ---------------- xproj = x @ w_ih.T + bias, stored [t][rowp][b] ----------------
__global__ void __launch_bounds__(256) k_xproj(
    const float* __restrict__ x, const float* __restrict__ w_ih,
    const float* __restrict__ b_ih, const float* __restrict__ b_hh)
{
    __shared__ float As[16][65];
    __shared__ float Bs[16][65];
    const int bm = blockIdx.y * 64, bn = blockIdx.x * 64;
    const int tid = threadIdx.x;
    const int tr = (tid >> 4) << 2, tc = (tid & 15) << 2;
    float acc[4][4] = {};
    for (int k0 = 0; k0 < DIsz; k0 += 16) {
        #pragma unroll
        for (int i0 = 0; i0 < 4; i0++) {
            int i = i0 * 256 + tid;
            int mm = i >> 4, kk = i & 15;
            int m = bm + mm, tt = m >> 5, bb = m & 31;
            As[kk][mm] = x[((size_t)bb * Tsz + tt) * DIsz + (k0 + kk)];
            Bs[kk][mm] = w_ih[(size_t)(bn + mm) * DIsz + (k0 + kk)];
        }
        __syncthreads();
        #pragma unroll
        for (int kk = 0; kk < 16; kk++) {
            float a[4] = {As[kk][tr], As[kk][tr+1], As[kk][tr+2], As[kk][tr+3]};
            float b[4] = {Bs[kk][tc], Bs[kk][tc+1], Bs[kk][tc+2], Bs[kk][tc+3]};
            #pragma unroll
            for (int i = 0; i < 4; i++)
                #pragma unroll
                for (int j = 0; j < 4; j++)
                    acc[i][j] = fmaf(a[i], b[j], acc[i][j]);
        }
        __syncthreads();
    }
    #pragma unroll
    for (int i = 0; i < 4; i++) {
        int m = bm + tr + i, tt = m >> 5, bb = m & 31;
        #pragma unroll
        for (int j = 0; j < 4; j++) {
            int n = bn + tc + j;
            int g = n >> 9, cd = (n >> 5) & 15, jj = n & 31;
            g_xt[((size_t)tt * 2048 + cd * 128 + g * 32 + jj) * 32 + bb]
                = acc[i][j] + b_ih[n] + b_hh[n];
        }
    }
}

// ---------------- persistent self-timed LSTM, fp16 1-MMA tensor GEMM ----------------
__global__ void __launch_bounds__(NTHR, 1) k_wave(
    const float* __restrict__ ca_b, float* __restrict__ out)
{
    extern __shared__ char smx[];

    const int tid  = threadIdx.x;
    const int lane = tid & 31;
    const int wid  = tid >> 5;
    const int cta  = blockIdx.x;
    const int gr = lane >> 2, c0 = (lane & 3) * 2;

    int layer, j0, nj, ci = 0;
    if (cta < 16) { layer = 0; nj = 32; j0 = cta * 32; }
    else {
        int r = cta - 16;
        layer = 1 + r / 44;
        ci = r % 44;
        cta_params(ci, nj, j0);
    }
    const int K  = (layer == 0) ? 512 : 1024;
    const int rs = K + 8;
    ushort* Bh = (ushort*)smx;
    float* part = (float*)(smx + PART_OFF);

    // warp roles: L0: mw=wid>>1 (0..7), np=wid&1, kw=0 (full K)
    //             CA: mw=wid>>2 (0..3), np=(wid>>1)&1, kw=wid&1 (K halves)
    int mw, np, kw;
    const uint4* wp4;
    float bias0 = 0.0f, bias1 = 0.0f;   // CA accumulator seeds (kw=0 only)
    if (layer == 0) {
        mw = wid >> 1; np = wid & 1; kw = 0;
        wp4 = (const uint4*)g_wA0 + ((size_t)(cta * 8 + mw)) * 1024 + lane;
    } else {
        mw = wid >> 2; np = (wid >> 1) & 1; kw = wid & 1;
        wp4 = (const uint4*)g_wAca + ((size_t)(((layer - 1) * 44 + ci) * 8 + mw * 2 + kw)) * 1024 + lane;
        if (kw == 0) {
            const float* cb = ca_b + (size_t)(layer - 1) * G5;
            int s0 = mw * 16 + gr, s1 = s0 + 8;
            if (s0 < 5 * nj) bias0 = cb[(s0 / nj) * 512 + j0 + (s0 % nj)];
            if (s1 < 5 * nj) bias1 = cb[(s1 / nj) * 512 + j0 + (s1 % nj)];
        }
    }
    const int kB = kw * 512 + c0;

    const int nch = K >> 3;            // uint4 chunks per B row
    const int chsh = (layer == 0) ? 6 : 7;

    for (int t = 0; t < Tsz; ++t) {
        // ---- wait for producers ----
        if (tid == 0) {
            if (layer == 0) {
                if (t > 0) {
                    volatile unsigned* p = &g_done[0];
                    while (*p < 16u * (unsigned)t) { }
                }
            } else {
                unsigned needl = (layer == 1 ? 16u : 44u) * (unsigned)(t + 1);
                volatile unsigned* pl = &g_done[layer - 1];
                while (*pl < needl) { }
                if (t > 0) {
                    volatile unsigned* po = &g_done[layer];
                    while (*po < 44u * (unsigned)t) { }
                }
            }
            __threadfence();
        }
        __syncthreads();

        // ---- stage H (fp16) into smem [b][k] ----
        {
            const uint4 zz = make_uint4(0, 0, 0, 0);
            for (int e = tid; e < 32 * nch; e += NTHR) {
                int b = e >> chsh, c = e & (nch - 1);
                int k8 = c * 8;
                const ushort* sh = nullptr;
                if (layer == 0) {
                    if (t > 0)
                        sh = g_hh + (((size_t)(t - 1)) * 32 + b) * 512 + k8;
                } else {
                    if (k8 < 512)
                        sh = g_hh + (((size_t)(layer - 1) * Tsz + t) * 32 + b) * 512 + k8;
                    else if (t > 0)
                        sh = g_hh + (((size_t)layer * Tsz + (t - 1)) * 32 + b) * 512 + (k8 - 512);
                }
                uint4 vh = sh ? __ldcg((const uint4*)sh) : zz;
                *(uint4*)(Bh + b * rs + k8) = vh;
            }
        }
        __syncthreads();

        // ---- tensor-core GEMM: 1 m-tile x 2 nt x 32 ks per warp ----
        {
            float d[2][4];
            // seed accumulators: L0 from xproj, CA(kw=0) from bias, else 0
            if (layer == 0) {
                const float* xb = g_xt + ((size_t)t * 2048 + cta * 128) * 32;
                int sl0 = mw * 16 + gr;
                #pragma unroll
                for (int ntp = 0; ntp < 2; ntp++) {
                    int bc = (np * 2 + ntp) * 8 + c0;
                    d[ntp][0] = __ldcg(xb + sl0 * 32 + bc);
                    d[ntp][1] = __ldcg(xb + sl0 * 32 + bc + 1);
                    d[ntp][2] = __ldcg(xb + (sl0 + 8) * 32 + bc);
                    d[ntp][3] = __ldcg(xb + (sl0 + 8) * 32 + bc + 1);
                }
            } else {
                #pragma unroll
                for (int ntp = 0; ntp < 2; ntp++) {
                    d[ntp][0] = bias0; d[ntp][1] = bias0;
                    d[ntp][2] = bias1; d[ntp][3] = bias1;
                }
            }
            bool active = !(t == 0 && (layer == 0 || kw == 1));
            if (active) {
                uint4 ah = __ldg(wp4);
                #pragma unroll
                for (int ks = 0; ks < 32; ks++) {
                    uint4 nx = ah;
                    if (ks < 31) nx = __ldg(wp4 + (ks + 1) * 32);
                    int k = kB + ks * 16;
                    #pragma unroll
                    for (int ntp = 0; ntp < 2; ntp++) {
                        int nt = np * 2 + ntp;
                        const ushort* ph = Bh + (nt * 8 + gr) * rs + k;
                        uint b0 = *(const uint*)ph, b1 = *(const uint*)(ph + 8);
                        mma_f16(d[ntp], ah, b0, b1);
                    }
                    ah = nx;
                }
            }
            float* pp = part + kw * PSTR;
            #pragma unroll
            for (int ntp = 0; ntp < 2; ntp++) {
                int sl0 = mw * 16 + gr;
                int bc = (np * 2 + ntp) * 8 + c0;
                pp[sl0 * 33 + bc]       = d[ntp][0];
                pp[sl0 * 33 + bc + 1]   = d[ntp][1];
                pp[(sl0 + 8) * 33 + bc]     = d[ntp][2];
                pp[(sl0 + 8) * 33 + bc + 1] = d[ntp][3];
            }
        }
        __syncthreads();

        // ---- activation + state update (pre-activations already complete) ----
        {
            size_t so = (((size_t)layer * Tsz + t)) * 32;
            float*  cout = g_c  + so * 512;
            ushort* hho  = g_hh + so * 512;
            const float* cprev = (t > 0) ? g_c + (((size_t)layer * Tsz + (t - 1)) * 32) * 512 : nullptr;
            if (layer == 0) {
                // single partial region; xproj already seeded
                for (int it = tid; it < 1024; it += NTHR) {
                    int b = it >> 5, jj = it & 31;
                    int j = cta * 32 + jj;
                    float i_ = part[(0 * 32 + jj) * 33 + b];
                    float f_ = part[(1 * 32 + jj) * 33 + b];
                    float gg = part[(2 * 32 + jj) * 33 + b];
                    float o_ = part[(3 * 32 + jj) * 33 + b];
                    float cp = cprev ? __ldcg(cprev + (size_t)b * 512 + j) : 0.0f;
                    float cv = sigf(i_) * tanhef(gg) + sigf(f_) * cp;
                    float hv = sigf(o_) * tanhef(cv);
                    cout[(size_t)b * 512 + j] = cv;
                    hho[(size_t)b * 512 + j]  = f16of(hv);
                }
            } else {
                const float* clow = g_c + (((size_t)(layer - 1) * Tsz + t) * 32) * 512;
                #define RED(SL, B) (part[(SL) * 33 + (B)] + part[PSTR + (SL) * 33 + (B)])
                for (int it = tid; it < nj * 32; it += NTHR) {
                    int b = it / nj, jj = it - b * nj;
                    int j = j0 + jj;
                    float i_ = RED(0 * nj + jj, b);
                    float fp = RED(1 * nj + jj, b);
                    float fl = RED(2 * nj + jj, b);
                    float u_ = RED(3 * nj + jj, b);
                    float o_ = RED(4 * nj + jj, b);
                    float cp = cprev ? __ldcg(cprev + (size_t)b * 512 + j) : 0.0f;
                    float cl = __ldcg(clow + (size_t)b * 512 + j);
                    float cv = cp * sigf(fp + 1.0f) + cl * sigf(fl + 1.0f) + tanhef(u_) * sigf(i_);
                    float hv = sigf(o_) * tanhef(cv);
                    cout[(size_t)b * 512 + j] = cv;
                    hho[(size_t)b * 512 + j]  = f16of(hv);
                    if (layer == 3) {
                        out[(size_t)b * Tsz * Hsz + (size_t)t * Hsz + j] = hv;
                        out[BTHn + (size_t)b * Tsz * Hsz + (size_t)t * Hsz + j] = cv;
                        if (t == Tsz - 1) {
                            out[2 * BTHn + (size_t)b * Hsz + j] = hv;
                            out[2 * BTHn + (size_t)Bsz * Hsz + (size_t)b * Hsz + j] = cv;
                        }
                    }
                }
                #undef RED
            }
        }
        __syncthreads();

        // ---- publish completion of step t ----
        if (tid == 0) {
            __threadfence();
            atomicAdd(&g_done[layer], 1u);
        }
    }
}

extern "C" void kernel_launch(void* const* d_in, const int* in_sizes, int n_in,
                              void* d_out, int out_size)
{
    const float* x    = (const float*)d_in[0];
    const float* w_ih = (const float*)d_in[1];
    const float* w_hh = (const float*)d_in[2];
    const float* b_ih = (const float*)d_in[3];
    const float* b_hh = (const float*)d_in[4];
    const float* ca_w = (const float*)d_in[5];
    const float* ca_b = (const float*)d_in[6];
    float* out = (float*)d_out;
    (void)in_sizes; (void)n_in; (void)out_size;

    k_fill<<<296, 256>>>(w_hh, ca_w);

    dim3 g(G4 / 64, (Tsz * Bsz) / 64);
    k_xproj<<<g, 256>>>(x, w_ih, b_ih, b_hh);

    const int smem_bytes = PART_OFF + 2 * PSTR * 4;  // 66048 + 33792 = 99840
    cudaFuncSetAttribute(k_wave, cudaFuncAttributeMaxDynamicSharedMemorySize, smem_bytes);
    k_wave<<<NCTA, NTHR, smem_bytes>>>(ca_b, out);
}

// round 13
// speedup vs baseline: 1.1726x; 1.0231x over previous
#include <cuda_runtime.h>
#include <cuda_fp16.h>
#include <cstdint>
#include <math.h>

#define Bsz 32
#define Tsz 512
#define DIsz 512
#define Hsz 512
#define G4 2048
#define G5 2560
#define NCTA 148
#define NTHR 512
#define BTHn ((size_t)32*512*512)

typedef unsigned int uint;
typedef unsigned short ushort;

// ---- static device scratch ----
// h stored as ONE fp16, layout [layer][t][b][k]; c fp32 [layer][t][b][j]
static __device__ __align__(16) ushort g_hh[(size_t)4*512*32*512];
static __device__ float g_c[(size_t)4*512*32*512];
static __device__ float g_xt[(size_t)512*2048*32];           // [t][rowp][b]
// single-fp16 weights in mma A-fragment order
static __device__ __align__(16) uint g_wA0[(size_t)16*8*32*128];     // L0: [cta][mw8][ks32][lane*4+reg]
static __device__ __align__(16) uint g_wAca[(size_t)132*8*32*128];   // CA: [lc][mw*2+kw][ks32][...]
static __device__ unsigned g_done[4];                        // per-layer step counters

#define PSTR 4224            // 128*33 floats per partial region
#define PART_OFF 66048       // bytes: B region = 32*1032 ushorts * 2B
#define CRING_OFF (PART_OFF + 2 * PSTR * 4)   // c ring: 2 x 1024 floats

// fast activations (MUFU-based, ~1e-7 error, correct saturation)
__device__ __forceinline__ float sigf(float x) {
    return __fdividef(1.0f, 1.0f + __expf(-x));
}
__device__ __forceinline__ float tanhef(float x) {
    return __fdividef(2.0f, 1.0f + __expf(-2.0f * x)) - 1.0f;
}

__device__ __forceinline__ ushort f16of(float w) {
    return __half_as_ushort(__float2half_rn(w));
}

__device__ __forceinline__ void mma_f16(float* d, const uint4& a, uint b0, uint b1) {
    asm volatile(
        "mma.sync.aligned.m16n8k16.row.col.f32.f16.f16.f32 "
        "{%0,%1,%2,%3},{%4,%5,%6,%7},{%8,%9},{%0,%1,%2,%3};"
        : "+f"(d[0]), "+f"(d[1]), "+f"(d[2]), "+f"(d[3])
        : "r"(a.x), "r"(a.y), "r"(a.z), "r"(a.w), "r"(b0), "r"(b1));
}

__device__ __forceinline__ void ldsm_x4(uint& r0, uint& r1, uint& r2, uint& r3, uint addr) {
    asm volatile(
        "ldmatrix.sync.aligned.m8n8.x4.shared.b16 {%0,%1,%2,%3}, [%4];"
        : "=r"(r0), "=r"(r1), "=r"(r2), "=r"(r3) : "r"(addr));
}

static __device__ __host__ __forceinline__ void cta_params(int ci, int& nj, int& j0) {
    if (ci < 28) { nj = 12; j0 = ci * 12; }
    else         { nj = 11; j0 = 336 + (ci - 28) * 11; }
}

// ---------------- weight fragment packing + counter reset ----------------
__global__ void __launch_bounds__(256) k_fill(const float* __restrict__ w_hh,
                                              const float* __restrict__ ca_w)
{
    size_t stride = (size_t)gridDim.x * blockDim.x;
    size_t i0 = (size_t)blockIdx.x * blockDim.x + threadIdx.x;
    if (i0 < 4) g_done[i0] = 0u;

    // L0: e = ((cta*8 + mw)*32 + ks)*128 + lane*4 + reg ; full K=512 per region
    const size_t N0 = (size_t)16*8*32*128;
    for (size_t e = i0; e < N0; e += stride) {
        int reg = (int)(e & 3), lane = (int)((e >> 2) & 31), ks = (int)((e >> 7) & 31);
        int mw = (int)((e >> 12) & 7), cta = (int)(e >> 15);
        int gr = lane >> 2, c0 = (lane & 3) * 2;
        int slot = mw * 16 + gr + (reg & 1) * 8;                 // 0..127
        int kk = ks * 16 + c0 + ((reg >> 1) & 1) * 8;            // 0..511
        int row = (slot >> 5) * 512 + cta * 32 + (slot & 31);
        float w0 = w_hh[(size_t)row * 512 + kk];
        float w1 = w_hh[(size_t)row * 512 + kk + 1];
        g_wA0[e] = (uint)f16of(w0) | ((uint)f16of(w1) << 16);
    }
    // CA: e = ((lc*8 + mw*2+kw)*32 + ks)*128 + lane*4 + reg ; K half (512) per region
    const size_t NC = (size_t)132*8*32*128;
    for (size_t e = i0; e < NC; e += stride) {
        int reg = (int)(e & 3), lane = (int)((e >> 2) & 31), ks = (int)((e >> 7) & 31);
        int mk = (int)((e >> 12) & 7), lc = (int)(e >> 15);
        int mw = mk >> 1, kw = mk & 1;
        int gr = lane >> 2, c0 = (lane & 3) * 2;
        int slot = mw * 16 + gr + (reg & 1) * 8;                 // 0..63
        int kk = kw * 512 + ks * 16 + c0 + ((reg >> 1) & 1) * 8; // 0..1023
        int ci = lc % 44, l = lc / 44;
        int nj, j0; cta_params(ci, nj, j0);
        float w0 = 0.0f, w1 = 0.0f;
        if (slot < 5 * nj) {
            int g = slot / nj, jj = slot - g * nj;
            int row = g * 512 + j0 + jj;
            w0 = ca_w[((size_t)l * G5 + row) * 1024 + kk];
            w1 = ca_w[((size_t)l * G5 + row) * 1024 + kk + 1];
        }
        g_wAca[e] = (uint)f16of(w0) | ((uint)f16of(w1) << 16);
    }
}

// ---------------- xproj = x @ w_ih.T + bias, stored [t][rowp][b] ----------------
__global__ void __launch_bounds__(256) k_xproj(
    const float* __restrict__ x, const float* __restrict__ w_ih,
    const float* __restrict__ b_ih, const float* __restrict__ b_hh)
{
    __shared__ float As[16][65];
    __shared__ float Bs[16][65];
    const int bm = blockIdx.y * 64, bn = blockIdx.x * 64;
    const int tid = threadIdx.x;
    const int tr = (tid >> 4) << 2, tc = (tid & 15) << 2;
    float acc[4][4] = {};
    for (int k0 = 0; k0 < DIsz; k0 += 16) {
        #pragma unroll
        for (int i0 = 0; i0 < 4; i0++) {
            int i = i0 * 256 + tid;
            int mm = i >> 4, kk = i & 15;
            int m = bm + mm, tt = m >> 5, bb = m & 31;
            As[kk][mm] = x[((size_t)bb * Tsz + tt) * DIsz + (k0 + kk)];
            Bs[kk][mm] = w_ih[(size_t)(bn + mm) * DIsz + (k0 + kk)];
        }
        __syncthreads();
        #pragma unroll
        for (int kk = 0; kk < 16; kk++) {
            float a[4] = {As[kk][tr], As[kk][tr+1], As[kk][tr+2], As[kk][tr+3]};
            float b[4] = {Bs[kk][tc], Bs[kk][tc+1], Bs[kk][tc+2], Bs[kk][tc+3]};
            #pragma unroll
            for (int i = 0; i < 4; i++)
                #pragma unroll
                for (int j = 0; j < 4; j++)
                    acc[i][j] = fmaf(a[i], b[j], acc[i][j]);
        }
        __syncthreads();
    }
    #pragma unroll
    for (int i = 0; i < 4; i++) {
        int m = bm + tr + i, tt = m >> 5, bb = m & 31;
        #pragma unroll
        for (int j = 0; j < 4; j++) {
            int n = bn + tc + j;
            int g = n >> 9, cd = (n >> 5) & 15, jj = n & 31;
            g_xt[((size_t)tt * 2048 + cd * 128 + g * 32 + jj) * 32 + bb]
                = acc[i][j] + b_ih[n] + b_hh[n];
        }
    }
}

// ---------------- persistent self-timed LSTM, fp16 1-MMA tensor GEMM ----------------
__global__ void __launch_bounds__(NTHR, 1) k_wave(
    const float* __restrict__ ca_b, float* __restrict__ out)
{
    extern __shared__ char smx[];

    const int tid  = threadIdx.x;
    const int lane = tid & 31;
    const int wid  = tid >> 5;
    const int cta  = blockIdx.x;
    const int gr = lane >> 2, c0 = (lane & 3) * 2;

    int layer, j0, nj, ci = 0;
    if (cta < 16) { layer = 0; nj = 32; j0 = cta * 32; }
    else {
        int r = cta - 16;
        layer = 1 + r / 44;
        ci = r % 44;
        cta_params(ci, nj, j0);
    }
    const int K  = (layer == 0) ? 512 : 1024;
    const int rs = K + 8;
    ushort* Bh = (ushort*)smx;
    float* part  = (float*)(smx + PART_OFF);
    float* cring = (float*)(smx + CRING_OFF);
    const uint bb32 = (uint)__cvta_generic_to_shared(smx);

    // warp roles: L0: mw=wid>>1 (0..7), np=wid&1, kw=0 (full K)
    //             CA: mw=wid>>2 (0..3), np=(wid>>1)&1, kw=wid&1 (K halves)
    int mw, np, kw;
    const uint4* wp4;
    float bias0 = 0.0f, bias1 = 0.0f;   // CA accumulator seeds (kw=0 only)
    if (layer == 0) {
        mw = wid >> 1; np = wid & 1; kw = 0;
        wp4 = (const uint4*)g_wA0 + ((size_t)(cta * 8 + mw)) * 1024 + lane;
    } else {
        mw = wid >> 2; np = (wid >> 1) & 1; kw = wid & 1;
        wp4 = (const uint4*)g_wAca + ((size_t)(((layer - 1) * 44 + ci) * 8 + mw * 2 + kw)) * 1024 + lane;
        if (kw == 0) {
            const float* cb = ca_b + (size_t)(layer - 1) * G5;
            int s0 = mw * 16 + gr, s1 = s0 + 8;
            if (s0 < 5 * nj) bias0 = cb[(s0 / nj) * 512 + j0 + (s0 % nj)];
            if (s1 < 5 * nj) bias1 = cb[(s1 / nj) * 512 + j0 + (s1 % nj)];
        }
    }
    // ldmatrix per-lane row address offset (bytes):
    //   matrix m = lane>>3: m0,m1 -> nt=np*2 (k, k+8); m2,m3 -> nt=np*2+1
    const int lrow = (np * 2 + ((lane >> 3) >> 1)) * 8 + (lane & 7);
    const uint ldsm_off = bb32 + (uint)(lrow * rs * 2 + ((lane >> 3) & 1) * 16);
    const int kwbase = kw * 512;

    const int nch = K >> 3;            // uint4 chunks per B row
    const int chsh = (layer == 0) ? 6 : 7;

    for (int t = 0; t < Tsz; ++t) {
        // ---- wait for producers ----
        if (tid == 0) {
            if (layer == 0) {
                if (t > 0) {
                    volatile unsigned* p = &g_done[0];
                    while (*p < 16u * (unsigned)t) { }
                }
            } else {
                unsigned needl = (layer == 1 ? 16u : 44u) * (unsigned)(t + 1);
                volatile unsigned* pl = &g_done[layer - 1];
                while (*pl < needl) { }
                if (t > 0) {
                    volatile unsigned* po = &g_done[layer];
                    while (*po < 44u * (unsigned)t) { }
                }
            }
            __threadfence();
        }
        __syncthreads();

        const bool active = !(t == 0 && (layer == 0 || kw == 1));
        uint4 ah;
        if (active) ah = __ldg(wp4);   // prefetch first weight frag during staging

        // ---- stage H (fp16) into smem [b][k] ----
        {
            const uint4 zz = make_uint4(0, 0, 0, 0);
            for (int e = tid; e < 32 * nch; e += NTHR) {
                int b = e >> chsh, c = e & (nch - 1);
                int k8 = c * 8;
                const ushort* sh = nullptr;
                if (layer == 0) {
                    if (t > 0)
                        sh = g_hh + (((size_t)(t - 1)) * 32 + b) * 512 + k8;
                } else {
                    if (k8 < 512)
                        sh = g_hh + (((size_t)(layer - 1) * Tsz + t) * 32 + b) * 512 + k8;
                    else if (t > 0)
                        sh = g_hh + (((size_t)layer * Tsz + (t - 1)) * 32 + b) * 512 + (k8 - 512);
                }
                uint4 vh = sh ? __ldcg((const uint4*)sh) : zz;
                *(uint4*)(Bh + b * rs + k8) = vh;
            }
        }
        __syncthreads();

        // ---- tensor-core GEMM: 1 m-tile x 2 nt x 32 ks per warp ----
        {
            float d[2][4];
            if (layer == 0) {
                const float* xb = g_xt + ((size_t)t * 2048 + cta * 128) * 32;
                int sl0 = mw * 16 + gr;
                #pragma unroll
                for (int ntp = 0; ntp < 2; ntp++) {
                    int bc = (np * 2 + ntp) * 8 + c0;
                    d[ntp][0] = __ldcg(xb + sl0 * 32 + bc);
                    d[ntp][1] = __ldcg(xb + sl0 * 32 + bc + 1);
                    d[ntp][2] = __ldcg(xb + (sl0 + 8) * 32 + bc);
                    d[ntp][3] = __ldcg(xb + (sl0 + 8) * 32 + bc + 1);
                }
            } else {
                #pragma unroll
                for (int ntp = 0; ntp < 2; ntp++) {
                    d[ntp][0] = bias0; d[ntp][1] = bias0;
                    d[ntp][2] = bias1; d[ntp][3] = bias1;
                }
            }
            if (active) {
                #pragma unroll
                for (int ks = 0; ks < 32; ks++) {
                    uint4 nx = ah;
                    if (ks < 31) nx = __ldg(wp4 + (ks + 1) * 32);
                    uint b00, b01, b10, b11;
                    ldsm_x4(b00, b01, b10, b11,
                            ldsm_off + (uint)((kwbase + ks * 16) * 2));
                    mma_f16(d[0], ah, b00, b01);
                    mma_f16(d[1], ah, b10, b11);
                    ah = nx;
                }
            }
            float* pp = part + kw * PSTR;
            #pragma unroll
            for (int ntp = 0; ntp < 2; ntp++) {
                int sl0 = mw * 16 + gr;
                int bc = (np * 2 + ntp) * 8 + c0;
                pp[sl0 * 33 + bc]       = d[ntp][0];
                pp[sl0 * 33 + bc + 1]   = d[ntp][1];
                pp[(sl0 + 8) * 33 + bc]     = d[ntp][2];
                pp[(sl0 + 8) * 33 + bc + 1] = d[ntp][3];
            }
        }
        __syncthreads();

        // ---- activation + state update (c_prev kept in smem ring) ----
        {
            size_t so = (((size_t)layer * Tsz + t)) * 32;
            float*  cout = g_c  + so * 512;
            ushort* hho  = g_hh + so * 512;
            float* ccur = cring + (t & 1) * 1024;
            float* cprv = cring + ((t & 1) ^ 1) * 1024;
            if (layer == 0) {
                for (int it = tid; it < 1024; it += NTHR) {
                    int b = it >> 5, jj = it & 31;
                    int j = cta * 32 + jj;
                    float i_ = part[(0 * 32 + jj) * 33 + b];
                    float f_ = part[(1 * 32 + jj) * 33 + b];
                    float gg = part[(2 * 32 + jj) * 33 + b];
                    float o_ = part[(3 * 32 + jj) * 33 + b];
                    float cp = (t > 0) ? cprv[it] : 0.0f;
                    float cv = sigf(i_) * tanhef(gg) + sigf(f_) * cp;
                    float hv = sigf(o_) * tanhef(cv);
                    ccur[it] = cv;
                    cout[(size_t)b * 512 + j] = cv;
                    hho[(size_t)b * 512 + j]  = f16of(hv);
                }
            } else {
                const float* clow = g_c + (((size_t)(layer - 1) * Tsz + t) * 32) * 512;
                #define RED(SL, B) (part[(SL) * 33 + (B)] + part[PSTR + (SL) * 33 + (B)])
                for (int it = tid; it < nj * 32; it += NTHR) {
                    int b = it / nj, jj = it - b * nj;
                    int j = j0 + jj;
                    float i_ = RED(0 * nj + jj, b);
                    float fp = RED(1 * nj + jj, b);
                    float fl = RED(2 * nj + jj, b);
                    float u_ = RED(3 * nj + jj, b);
                    float o_ = RED(4 * nj + jj, b);
                    float cp = (t > 0) ? cprv[it] : 0.0f;
                    float cl = __ldcg(clow + (size_t)b * 512 + j);
                    float cv = cp * sigf(fp + 1.0f) + cl * sigf(fl + 1.0f) + tanhef(u_) * sigf(i_);
                    float hv = sigf(o_) * tanhef(cv);
                    ccur[it] = cv;
                    if (layer != 3) cout[(size_t)b * 512 + j] = cv;
                    hho[(size_t)b * 512 + j]  = f16of(hv);
                    if (layer == 3) {
                        out[(size_t)b * Tsz * Hsz + (size_t)t * Hsz + j] = hv;
                        out[BTHn + (size_t)b * Tsz * Hsz + (size_t)t * Hsz + j] = cv;
                        if (t == Tsz - 1) {
                            out[2 * BTHn + (size_t)b * Hsz + j] = hv;
                            out[2 * BTHn + (size_t)Bsz * Hsz + (size_t)b * Hsz + j] = cv;
                        }
                    }
                }
                #undef RED
            }
        }
        __syncthreads();

        // ---- publish completion of step t ----
        if (tid == 0) {
            __threadfence();
            atomicAdd(&g_done[layer], 1u);
        }
    }
}

extern "C" void kernel_launch(void* const* d_in, const int* in_sizes, int n_in,
                              void* d_out, int out_size)
{
    const float* x    = (const float*)d_in[0];
    const float* w_ih = (const float*)d_in[1];
    const float* w_hh = (const float*)d_in[2];
    const float* b_ih = (const float*)d_in[3];
    const float* b_hh = (const float*)d_in[4];
    const float* ca_w = (const float*)d_in[5];
    const float* ca_b = (const float*)d_in[6];
    float* out = (float*)d_out;
    (void)in_sizes; (void)n_in; (void)out_size;

    k_fill<<<296, 256>>>(w_hh, ca_w);

    dim3 g(G4 / 64, (Tsz * Bsz) / 64);
    k_xproj<<<g, 256>>>(x, w_ih, b_ih, b_hh);

    const int smem_bytes = CRING_OFF + 2 * 1024 * 4;  // 99840 + 8192 = 108032
    cudaFuncSetAttribute(k_wave, cudaFuncAttributeMaxDynamicSharedMemorySize, smem_bytes);
    k_wave<<<NCTA, NTHR, smem_bytes>>>(ca_b, out);
}

// round 14
// speedup vs baseline: 1.2306x; 1.0495x over previous
#include <cuda_runtime.h>
#include <cuda_fp16.h>
#include <cstdint>
#include <math.h>

#define Bsz 32
#define Tsz 512
#define DIsz 512
#define Hsz 512
#define G4 2048
#define G5 2560
#define NCTA 148
#define NTHR 512
#define BTHn ((size_t)32*512*512)

typedef unsigned int uint;
typedef unsigned short ushort;

// ---- static device scratch ----
// h stored as ONE fp16, layout [layer][t][b][k]; c fp32 [layer][t][b][j]
static __device__ __align__(16) ushort g_hh[(size_t)4*512*32*512];
static __device__ float g_c[(size_t)4*512*32*512];
static __device__ float g_xt[(size_t)512*2048*32];           // [t][rowp][b]
// single-fp16 weights in mma A-fragment order
static __device__ __align__(16) uint g_wA0[(size_t)16*8*32*128];     // L0: [cta][mw8][ks32][lane*4+reg]
static __device__ __align__(16) uint g_wAca[(size_t)132*8*32*128];   // CA: [lc][mw*2+kw][ks32][...]
static __device__ unsigned g_done[4];                        // per-layer step counters

#define PSTR 4224            // 128*33 floats per partial region
#define PART_OFF 66048       // bytes: B region = 32*1032 ushorts * 2B
#define CRING_OFF (PART_OFF + 2 * PSTR * 4)   // c ring: 2 x 1024 floats

// fast activations (MUFU-based, ~1e-7 error, correct saturation)
__device__ __forceinline__ float sigf(float x) {
    return __fdividef(1.0f, 1.0f + __expf(-x));
}
__device__ __forceinline__ float tanhef(float x) {
    return __fdividef(2.0f, 1.0f + __expf(-2.0f * x)) - 1.0f;
}

__device__ __forceinline__ ushort f16of(float w) {
    return __half_as_ushort(__float2half_rn(w));
}

__device__ __forceinline__ void mma_f16(float* d, const uint4& a, uint b0, uint b1) {
    asm volatile(
        "mma.sync.aligned.m16n8k16.row.col.f32.f16.f16.f32 "
        "{%0,%1,%2,%3},{%4,%5,%6,%7},{%8,%9},{%0,%1,%2,%3};"
        : "+f"(d[0]), "+f"(d[1]), "+f"(d[2]), "+f"(d[3])
        : "r"(a.x), "r"(a.y), "r"(a.z), "r"(a.w), "r"(b0), "r"(b1));
}

__device__ __forceinline__ void ldsm_x4(uint& r0, uint& r1, uint& r2, uint& r3, uint addr) {
    asm volatile(
        "ldmatrix.sync.aligned.m8n8.x4.shared.b16 {%0,%1,%2,%3}, [%4];"
        : "=r"(r0), "=r"(r1), "=r"(r2), "=r"(r3) : "r"(addr));
}

static __device__ __host__ __forceinline__ void cta_params(int ci, int& nj, int& j0) {
    if (ci < 28) { nj = 12; j0 = ci * 12; }
    else         { nj = 11; j0 = 336 + (ci - 28) * 11; }
}

// ---------------- weight fragment packing + counter reset ----------------
__global__ void __launch_bounds__(256) k_fill(const float* __restrict__ w_hh,
                                              const float* __restrict__ ca_w)
{
    size_t stride = (size_t)gridDim.x * blockDim.x;
    size_t i0 = (size_t)blockIdx.x * blockDim.x + threadIdx.x;
    if (i0 < 4) g_done[i0] = 0u;

    // L0: e = ((cta*8 + mw)*32 + ks)*128 + lane*4 + reg ; full K=512 per region
    const size_t N0 = (size_t)16*8*32*128;
    for (size_t e = i0; e < N0; e += stride) {
        int reg = (int)(e & 3), lane = (int)((e >> 2) & 31), ks = (int)((e >> 7) & 31);
        int mw = (int)((e >> 12) & 7), cta = (int)(e >> 15);
        int gr = lane >> 2, c0 = (lane & 3) * 2;
        int slot = mw * 16 + gr + (reg & 1) * 8;                 // 0..127
        int kk = ks * 16 + c0 + ((reg >> 1) & 1) * 8;            // 0..511
        int row = (slot >> 5) * 512 + cta * 32 + (slot & 31);
        float w0 = w_hh[(size_t)row * 512 + kk];
        float w1 = w_hh[(size_t)row * 512 + kk + 1];
        g_wA0[e] = (uint)f16of(w0) | ((uint)f16of(w1) << 16);
    }
    // CA: e = ((lc*8 + mw*2+kw)*32 + ks)*128 + lane*4 + reg ; K half (512) per region
    const size_t NC = (size_t)132*8*32*128;
    for (size_t e = i0; e < NC; e += stride) {
        int reg = (int)(e & 3), lane = (int)((e >> 2) & 31), ks = (int)((e >> 7) & 31);
        int mk = (int)((e >> 12) & 7), lc = (int)(e >> 15);
        int mw = mk >> 1, kw = mk & 1;
        int gr = lane >> 2, c0 = (lane & 3) * 2;
        int slot = mw * 16 + gr + (reg & 1) * 8;                 // 0..63
        int kk = kw * 512 + ks * 16 + c0 + ((reg >> 1) & 1) * 8; // 0..1023
        int ci = lc % 44, l = lc / 44;
        int nj, j0; cta_params(ci, nj, j0);
        float w0 = 0.0f, w1 = 0.0f;
        if (slot < 5 * nj) {
            int g = slot / nj, jj = slot - g * nj;
            int row = g * 512 + j0 + jj;
            w0 = ca_w[((size_t)l * G5 + row) * 1024 + kk];
            w1 = ca_w[((size_t)l * G5 + row) * 1024 + kk + 1];
        }
        g_wAca[e] = (uint)f16of(w0) | ((uint)f16of(w1) << 16);
    }
}

// ---------------- xproj = x @ w_ih.T + bias, stored [t][rowp][b] ----------------
__global__ void __launch_bounds__(256) k_xproj(
    const float* __restrict__ x, const float* __restrict__ w_ih,
    const float* __restrict__ b_ih, const float* __restrict__ b_hh)
{
    __shared__ float As[16][65];
    __shared__ float Bs[16][65];
    const int bm = blockIdx.y * 64, bn = blockIdx.x * 64;
    const int tid = threadIdx.x;
    const int tr = (tid >> 4) << 2, tc = (tid & 15) << 2;
    float acc[4][4] = {};
    for (int k0 = 0; k0 < DIsz; k0 += 16) {
        #pragma unroll
        for (int i0 = 0; i0 < 4; i0++) {
            int i = i0 * 256 + tid;
            int mm = i >> 4, kk = i & 15;
            int m = bm + mm, tt = m >> 5, bb = m & 31;
            As[kk][mm] = x[((size_t)bb * Tsz + tt) * DIsz + (k0 + kk)];
            Bs[kk][mm] = w_ih[(size_t)(bn + mm) * DIsz + (k0 + kk)];
        }
        __syncthreads();
        #pragma unroll
        for (int kk = 0; kk < 16; kk++) {
            float a[4] = {As[kk][tr], As[kk][tr+1], As[kk][tr+2], As[kk][tr+3]};
            float b[4] = {Bs[kk][tc], Bs[kk][tc+1], Bs[kk][tc+2], Bs[kk][tc+3]};
            #pragma unroll
            for (int i = 0; i < 4; i++)
                #pragma unroll
                for (int j = 0; j < 4; j++)
                    acc[i][j] = fmaf(a[i], b[j], acc[i][j]);
        }
        __syncthreads();
    }
    #pragma unroll
    for (int i = 0; i < 4; i++) {
        int m = bm + tr + i, tt = m >> 5, bb = m & 31;
        #pragma unroll
        for (int j = 0; j < 4; j++) {
            int n = bn + tc + j;
            int g = n >> 9, cd = (n >> 5) & 15, jj = n & 31;
            g_xt[((size_t)tt * 2048 + cd * 128 + g * 32 + jj) * 32 + bb]
                = acc[i][j] + b_ih[n] + b_hh[n];
        }
    }
}

// ---------------- persistent self-timed LSTM, fp16 1-MMA tensor GEMM ----------------
__global__ void __launch_bounds__(NTHR, 1) k_wave(
    const float* __restrict__ ca_b, float* __restrict__ out)
{
    extern __shared__ char smx[];

    const int tid  = threadIdx.x;
    const int lane = tid & 31;
    const int wid  = tid >> 5;
    const int cta  = blockIdx.x;
    const int gr = lane >> 2, c0 = (lane & 3) * 2;

    int layer, j0, nj, ci = 0;
    if (cta < 16) { layer = 0; nj = 32; j0 = cta * 32; }
    else {
        int r = cta - 16;
        layer = 1 + r / 44;
        ci = r % 44;
        cta_params(ci, nj, j0);
    }
    const int K  = (layer == 0) ? 512 : 1024;
    const int rs = K + 8;
    ushort* Bh = (ushort*)smx;
    float* part  = (float*)(smx + PART_OFF);
    float* cring = (float*)(smx + CRING_OFF);
    const uint bb32 = (uint)__cvta_generic_to_shared(smx);

    // warp roles: L0: mw=wid>>1 (0..7), np=wid&1, kw=0 (full K)
    //             CA: mw=wid>>2 (0..3), np=(wid>>1)&1, kw=wid&1 (K halves)
    int mw, np, kw;
    const uint4* wp4;
    float bias0 = 0.0f, bias1 = 0.0f;   // CA accumulator seeds (kw=0 only)
    if (layer == 0) {
        mw = wid >> 1; np = wid & 1; kw = 0;
        wp4 = (const uint4*)g_wA0 + ((size_t)(cta * 8 + mw)) * 1024 + lane;
    } else {
        mw = wid >> 2; np = (wid >> 1) & 1; kw = wid & 1;
        wp4 = (const uint4*)g_wAca + ((size_t)(((layer - 1) * 44 + ci) * 8 + mw * 2 + kw)) * 1024 + lane;
        if (kw == 0) {
            const float* cb = ca_b + (size_t)(layer - 1) * G5;
            int s0 = mw * 16 + gr, s1 = s0 + 8;
            if (s0 < 5 * nj) bias0 = cb[(s0 / nj) * 512 + j0 + (s0 % nj)];
            if (s1 < 5 * nj) bias1 = cb[(s1 / nj) * 512 + j0 + (s1 % nj)];
        }
    }
    // ldmatrix per-lane row address offset (bytes)
    const int lrow = (np * 2 + ((lane >> 3) >> 1)) * 8 + (lane & 7);
    const uint ldsm_off = bb32 + (uint)(lrow * rs * 2 + ((lane >> 3) & 1) * 16);
    const int kwbase = kw * 512;

    for (int t = 0; t < Tsz; ++t) {
        const bool active = !(t == 0 && (layer == 0 || kw == 1));

        // 4-deep weight prefetch ring — issue before any waiting/staging work
        uint4 w0r, w1r, w2r, w3r;
        if (active) {
            w0r = __ldg(wp4);
            w1r = __ldg(wp4 + 1 * 32);
            w2r = __ldg(wp4 + 2 * 32);
            w3r = __ldg(wp4 + 3 * 32);
        }

        float d[2][4];

        if (layer == 0) {
            // ---- wait own-layer ----
            if (tid == 0 && t > 0) {
                volatile unsigned* p = &g_done[0];
                while (*p < 16u * (unsigned)t) { }
                __threadfence();
            }
            __syncthreads();
            // seed accumulators from xproj (issued before staging to overlap)
            {
                const float* xb = g_xt + ((size_t)t * 2048 + cta * 128) * 32;
                int sl0 = mw * 16 + gr;
                #pragma unroll
                for (int ntp = 0; ntp < 2; ntp++) {
                    int bc = (np * 2 + ntp) * 8 + c0;
                    d[ntp][0] = __ldcg(xb + sl0 * 32 + bc);
                    d[ntp][1] = __ldcg(xb + sl0 * 32 + bc + 1);
                    d[ntp][2] = __ldcg(xb + (sl0 + 8) * 32 + bc);
                    d[ntp][3] = __ldcg(xb + (sl0 + 8) * 32 + bc + 1);
                }
            }
            // ---- stage h(t-1) ----
            {
                const uint4 zz = make_uint4(0, 0, 0, 0);
                for (int e = tid; e < 32 * 64; e += NTHR) {
                    int b = e >> 6, c = e & 63;
                    int k8 = c * 8;
                    uint4 vh = (t > 0)
                        ? __ldcg((const uint4*)(g_hh + (((size_t)(t - 1)) * 32 + b) * 512 + k8))
                        : zz;
                    *(uint4*)(Bh + b * rs + k8) = vh;
                }
            }
            __syncthreads();
        } else {
            #pragma unroll
            for (int ntp = 0; ntp < 2; ntp++) {
                d[ntp][0] = bias0; d[ntp][1] = bias0;
                d[ntp][2] = bias1; d[ntp][3] = bias1;
            }
            // ---- wait lower layer; stage low half ----
            if (tid == 0) {
                unsigned needl = (layer == 1 ? 16u : 44u) * (unsigned)(t + 1);
                volatile unsigned* pl = &g_done[layer - 1];
                while (*pl < needl) { }
                __threadfence();
            }
            __syncthreads();
            for (int e = tid; e < 32 * 64; e += NTHR) {
                int b = e >> 6, c = e & 63;
                int k8 = c * 8;
                uint4 vh = __ldcg((const uint4*)(
                    g_hh + (((size_t)(layer - 1) * Tsz + t) * 32 + b) * 512 + k8));
                *(uint4*)(Bh + b * rs + k8) = vh;
            }
            // ---- wait own layer; stage own half ----
            if (tid == 0 && t > 0) {
                volatile unsigned* po = &g_done[layer];
                while (*po < 44u * (unsigned)t) { }
                __threadfence();
            }
            __syncthreads();
            {
                const uint4 zz = make_uint4(0, 0, 0, 0);
                for (int e = tid; e < 32 * 64; e += NTHR) {
                    int b = e >> 6, c = e & 63;
                    int k8 = c * 8;
                    uint4 vh = (t > 0)
                        ? __ldcg((const uint4*)(
                              g_hh + (((size_t)layer * Tsz + (t - 1)) * 32 + b) * 512 + k8))
                        : zz;
                    *(uint4*)(Bh + b * rs + 512 + k8) = vh;
                }
            }
            __syncthreads();
        }

        // ---- tensor-core GEMM: 1 m-tile x 2 nt x 32 ks per warp ----
        if (active) {
            #pragma unroll
            for (int ks = 0; ks < 32; ks++) {
                uint4 a;
                switch (ks & 3) {
                    case 0: a = w0r; if (ks + 4 < 32) w0r = __ldg(wp4 + (ks + 4) * 32); break;
                    case 1: a = w1r; if (ks + 4 < 32) w1r = __ldg(wp4 + (ks + 4) * 32); break;
                    case 2: a = w2r; if (ks + 4 < 32) w2r = __ldg(wp4 + (ks + 4) * 32); break;
                    default: a = w3r; if (ks + 4 < 32) w3r = __ldg(wp4 + (ks + 4) * 32); break;
                }
                uint b00, b01, b10, b11;
                ldsm_x4(b00, b01, b10, b11,
                        ldsm_off + (uint)((kwbase + ks * 16) * 2));
                mma_f16(d[0], a, b00, b01);
                mma_f16(d[1], a, b10, b11);
            }
        }
        {
            float* pp = part + kw * PSTR;
            #pragma unroll
            for (int ntp = 0; ntp < 2; ntp++) {
                int sl0 = mw * 16 + gr;
                int bc = (np * 2 + ntp) * 8 + c0;
                pp[sl0 * 33 + bc]       = d[ntp][0];
                pp[sl0 * 33 + bc + 1]   = d[ntp][1];
                pp[(sl0 + 8) * 33 + bc]     = d[ntp][2];
                pp[(sl0 + 8) * 33 + bc + 1] = d[ntp][3];
            }
        }
        __syncthreads();

        // ---- activation + state update (c_prev kept in smem ring) ----
        {
            size_t so = (((size_t)layer * Tsz + t)) * 32;
            float*  cout = g_c  + so * 512;
            ushort* hho  = g_hh + so * 512;
            float* ccur = cring + (t & 1) * 1024;
            float* cprv = cring + ((t & 1) ^ 1) * 1024;
            if (layer == 0) {
                for (int it = tid; it < 1024; it += NTHR) {
                    int b = it >> 5, jj = it & 31;
                    int j = cta * 32 + jj;
                    float i_ = part[(0 * 32 + jj) * 33 + b];
                    float f_ = part[(1 * 32 + jj) * 33 + b];
                    float gg = part[(2 * 32 + jj) * 33 + b];
                    float o_ = part[(3 * 32 + jj) * 33 + b];
                    float cp = (t > 0) ? cprv[it] : 0.0f;
                    float cv = sigf(i_) * tanhef(gg) + sigf(f_) * cp;
                    float hv = sigf(o_) * tanhef(cv);
                    ccur[it] = cv;
                    cout[(size_t)b * 512 + j] = cv;
                    hho[(size_t)b * 512 + j]  = f16of(hv);
                }
            } else {
                const float* clow = g_c + (((size_t)(layer - 1) * Tsz + t) * 32) * 512;
                #define RED(SL, B) (part[(SL) * 33 + (B)] + part[PSTR + (SL) * 33 + (B)])
                for (int it = tid; it < nj * 32; it += NTHR) {
                    int b = it / nj, jj = it - b * nj;
                    int j = j0 + jj;
                    float i_ = RED(0 * nj + jj, b);
                    float fp = RED(1 * nj + jj, b);
                    float fl = RED(2 * nj + jj, b);
                    float u_ = RED(3 * nj + jj, b);
                    float o_ = RED(4 * nj + jj, b);
                    float cp = (t > 0) ? cprv[it] : 0.0f;
                    float cl = __ldcg(clow + (size_t)b * 512 + j);
                    float cv = cp * sigf(fp + 1.0f) + cl * sigf(fl + 1.0f) + tanhef(u_) * sigf(i_);
                    float hv = sigf(o_) * tanhef(cv);
                    ccur[it] = cv;
                    if (layer != 3) cout[(size_t)b * 512 + j] = cv;
                    hho[(size_t)b * 512 + j]  = f16of(hv);
                    if (layer == 3) {
                        out[(size_t)b * Tsz * Hsz + (size_t)t * Hsz + j] = hv;
                        out[BTHn + (size_t)b * Tsz * Hsz + (size_t)t * Hsz + j] = cv;
                        if (t == Tsz - 1) {
                            out[2 * BTHn + (size_t)b * Hsz + j] = hv;
                            out[2 * BTHn + (size_t)Bsz * Hsz + (size_t)b * Hsz + j] = cv;
                        }
                    }
                }
                #undef RED
            }
        }
        __syncthreads();

        // ---- publish completion of step t (release semantics) ----
        if (tid == 0) {
            asm volatile("red.release.gpu.global.add.u32 [%0], %1;"
                         :: "l"(&g_done[layer]), "r"(1u) : "memory");
        }
    }
}

extern "C" void kernel_launch(void* const* d_in, const int* in_sizes, int n_in,
                              void* d_out, int out_size)
{
    const float* x    = (const float*)d_in[0];
    const float* w_ih = (const float*)d_in[1];
    const float* w_hh = (const float*)d_in[2];
    const float* b_ih = (const float*)d_in[3];
    const float* b_hh = (const float*)d_in[4];
    const float* ca_w = (const float*)d_in[5];
    const float* ca_b = (const float*)d_in[6];
    float* out = (float*)d_out;
    (void)in_sizes; (void)n_in; (void)out_size;

    k_fill<<<296, 256>>>(w_hh, ca_w);

    dim3 g(G4 / 64, (Tsz * Bsz) / 64);
    k_xproj<<<g, 256>>>(x, w_ih, b_ih, b_hh);

    const int smem_bytes = CRING_OFF + 2 * 1024 * 4;  // 108032
    cudaFuncSetAttribute(k_wave, cudaFuncAttributeMaxDynamicSharedMemorySize, smem_bytes);
    k_wave<<<NCTA, NTHR, smem_bytes>>>(ca_b, out);
}

// round 15
// speedup vs baseline: 1.4413x; 1.1712x over previous
#include <cuda_runtime.h>
#include <cuda_fp16.h>
#include <cstdint>
#include <math.h>

#define Bsz 32
#define Tsz 512
#define DIsz 512
#define Hsz 512
#define G4 2048
#define G5 2560
#define NCTA 148
#define NTHR 512
#define BTHn ((size_t)32*512*512)

typedef unsigned int uint;
typedef unsigned short ushort;

// ---- static device scratch ----
static __device__ __align__(16) ushort g_hh[(size_t)4*512*32*512];   // h fp16 [l][t][b][k]
static __device__ float g_c[(size_t)4*512*32*512];                   // c fp32 [l][t][b][j]
static __device__ float g_xt[(size_t)512*2048*32];                   // [t][rowp][b]
static __device__ __align__(16) uint g_wA0[(size_t)16*8*32*128];     // L0 frags
static __device__ __align__(16) uint g_wAca[(size_t)132*8*32*128];   // CA frags
static __device__ unsigned g_flag[4*64*32];                          // per-CTA step flags (128B apart)

#define PSTR 4224            // 128*33 floats per partial region
#define PART_OFF 66048       // bytes: B region = 32*1032 ushorts * 2B
#define CRING_OFF (PART_OFF + 2 * PSTR * 4)   // c ring: 2 x 1024 floats

__device__ __forceinline__ float sigf(float x) {
    return __fdividef(1.0f, 1.0f + __expf(-x));
}
__device__ __forceinline__ float tanhef(float x) {
    return __fdividef(2.0f, 1.0f + __expf(-2.0f * x)) - 1.0f;
}
__device__ __forceinline__ ushort f16of(float w) {
    return __half_as_ushort(__float2half_rn(w));
}
__device__ __forceinline__ unsigned ld_acq(const unsigned* p) {
    unsigned v;
    asm volatile("ld.acquire.gpu.global.u32 %0, [%1];" : "=r"(v) : "l"(p) : "memory");
    return v;
}
__device__ __forceinline__ void st_rel(unsigned* p, unsigned v) {
    asm volatile("st.release.gpu.global.u32 [%0], %1;" :: "l"(p), "r"(v) : "memory");
}
// warp-cooperative poll: wait until all nc flags (stride 32 uints) >= target
__device__ __forceinline__ void poll_flags(const unsigned* base, int nc, unsigned target) {
    int lane = threadIdx.x & 31;
    const unsigned* p1 = base + lane * 32;
    const unsigned* p2 = base + (lane + 32) * 32;
    bool n1 = lane < nc, n2 = (lane + 32) < nc;
    bool ok;
    do {
        ok = true;
        if (n1 && ld_acq(p1) < target) ok = false;
        if (n2 && ld_acq(p2) < target) ok = false;
    } while (__all_sync(0xffffffffu, ok) == 0);
}

__device__ __forceinline__ void mma_f16(float* d, const uint4& a, uint b0, uint b1) {
    asm volatile(
        "mma.sync.aligned.m16n8k16.row.col.f32.f16.f16.f32 "
        "{%0,%1,%2,%3},{%4,%5,%6,%7},{%8,%9},{%0,%1,%2,%3};"
        : "+f"(d[0]), "+f"(d[1]), "+f"(d[2]), "+f"(d[3])
        : "r"(a.x), "r"(a.y), "r"(a.z), "r"(a.w), "r"(b0), "r"(b1));
}
__device__ __forceinline__ void ldsm_x4(uint& r0, uint& r1, uint& r2, uint& r3, uint addr) {
    asm volatile(
        "ldmatrix.sync.aligned.m8n8.x4.shared.b16 {%0,%1,%2,%3}, [%4];"
        : "=r"(r0), "=r"(r1), "=r"(r2), "=r"(r3) : "r"(addr));
}
#define BARX(ID) asm volatile("bar.sync %0, 256;" :: "r"(ID) : "memory")

static __device__ __host__ __forceinline__ void cta_params(int ci, int& nj, int& j0) {
    if (ci < 28) { nj = 12; j0 = ci * 12; }
    else         { nj = 11; j0 = 336 + (ci - 28) * 11; }
}

// ---------------- weight fragment packing + flag reset ----------------
__global__ void __launch_bounds__(256) k_fill(const float* __restrict__ w_hh,
                                              const float* __restrict__ ca_w)
{
    size_t stride = (size_t)gridDim.x * blockDim.x;
    size_t i0 = (size_t)blockIdx.x * blockDim.x + threadIdx.x;
    for (size_t e = i0; e < 4 * 64 * 32; e += stride) g_flag[e] = 0u;

    const size_t N0 = (size_t)16*8*32*128;
    for (size_t e = i0; e < N0; e += stride) {
        int reg = (int)(e & 3), lane = (int)((e >> 2) & 31), ks = (int)((e >> 7) & 31);
        int mw = (int)((e >> 12) & 7), cta = (int)(e >> 15);
        int gr = lane >> 2, c0 = (lane & 3) * 2;
        int slot = mw * 16 + gr + (reg & 1) * 8;
        int kk = ks * 16 + c0 + ((reg >> 1) & 1) * 8;
        int row = (slot >> 5) * 512 + cta * 32 + (slot & 31);
        float w0 = w_hh[(size_t)row * 512 + kk];
        float w1 = w_hh[(size_t)row * 512 + kk + 1];
        g_wA0[e] = (uint)f16of(w0) | ((uint)f16of(w1) << 16);
    }
    const size_t NC = (size_t)132*8*32*128;
    for (size_t e = i0; e < NC; e += stride) {
        int reg = (int)(e & 3), lane = (int)((e >> 2) & 31), ks = (int)((e >> 7) & 31);
        int mk = (int)((e >> 12) & 7), lc = (int)(e >> 15);
        int mw = mk >> 1, kw = mk & 1;
        int gr = lane >> 2, c0 = (lane & 3) * 2;
        int slot = mw * 16 + gr + (reg & 1) * 8;
        int kk = kw * 512 + ks * 16 + c0 + ((reg >> 1) & 1) * 8;
        int ci = lc % 44, l = lc / 44;
        int nj, j0; cta_params(ci, nj, j0);
        float w0 = 0.0f, w1 = 0.0f;
        if (slot < 5 * nj) {
            int g = slot / nj, jj = slot - g * nj;
            int row = g * 512 + j0 + jj;
            w0 = ca_w[((size_t)l * G5 + row) * 1024 + kk];
            w1 = ca_w[((size_t)l * G5 + row) * 1024 + kk + 1];
        }
        g_wAca[e] = (uint)f16of(w0) | ((uint)f16of(w1) << 16);
    }
}

// ---------------- xproj = x @ w_ih.T + bias, stored [t][rowp][b] ----------------
__global__ void __launch_bounds__(256) k_xproj(
    const float* __restrict__ x, const float* __restrict__ w_ih,
    const float* __restrict__ b_ih, const float* __restrict__ b_hh)
{
    __shared__ float As[16][65];
    __shared__ float Bs[16][65];
    const int bm = blockIdx.y * 64, bn = blockIdx.x * 64;
    const int tid = threadIdx.x;
    const int tr = (tid >> 4) << 2, tc = (tid & 15) << 2;
    float acc[4][4] = {};
    for (int k0 = 0; k0 < DIsz; k0 += 16) {
        #pragma unroll
        for (int i0 = 0; i0 < 4; i0++) {
            int i = i0 * 256 + tid;
            int mm = i >> 4, kk = i & 15;
            int m = bm + mm, tt = m >> 5, bb = m & 31;
            As[kk][mm] = x[((size_t)bb * Tsz + tt) * DIsz + (k0 + kk)];
            Bs[kk][mm] = w_ih[(size_t)(bn + mm) * DIsz + (k0 + kk)];
        }
        __syncthreads();
        #pragma unroll
        for (int kk = 0; kk < 16; kk++) {
            float a[4] = {As[kk][tr], As[kk][tr+1], As[kk][tr+2], As[kk][tr+3]};
            float b[4] = {Bs[kk][tc], Bs[kk][tc+1], Bs[kk][tc+2], Bs[kk][tc+3]};
            #pragma unroll
            for (int i = 0; i < 4; i++)
                #pragma unroll
                for (int j = 0; j < 4; j++)
                    acc[i][j] = fmaf(a[i], b[j], acc[i][j]);
        }
        __syncthreads();
    }
    #pragma unroll
    for (int i = 0; i < 4; i++) {
        int m = bm + tr + i, tt = m >> 5, bb = m & 31;
        #pragma unroll
        for (int j = 0; j < 4; j++) {
            int n = bn + tc + j;
            int g = n >> 9, cd = (n >> 5) & 15, jj = n & 31;
            g_xt[((size_t)tt * 2048 + cd * 128 + g * 32 + jj) * 32 + bb]
                = acc[i][j] + b_ih[n] + b_hh[n];
        }
    }
}

// ---------------- persistent self-timed LSTM, warp-group-specialized ----------------
__global__ void __launch_bounds__(NTHR, 1) k_wave(
    const float* __restrict__ ca_b, float* __restrict__ out)
{
    extern __shared__ char smx[];

    const int tid  = threadIdx.x;
    const int lane = tid & 31;
    const int wid  = tid >> 5;
    const int cta  = blockIdx.x;
    const int gr = lane >> 2, c0 = (lane & 3) * 2;

    int layer, j0, nj, ci = 0;
    if (cta < 16) { layer = 0; nj = 32; j0 = cta * 32; }
    else {
        int r = cta - 16;
        layer = 1 + r / 44;
        ci = r % 44;
        cta_params(ci, nj, j0);
    }
    const int K  = (layer == 0) ? 512 : 1024;
    const int rs = K + 8;
    ushort* Bh = (ushort*)smx;
    float* part  = (float*)(smx + PART_OFF);
    float* cring = (float*)(smx + CRING_OFF);
    const uint bb32 = (uint)__cvta_generic_to_shared(smx);

    // warp roles: L0: mw=wid>>1 (0..7), np=wid&1, kw=0
    //             CA: kw=wid>>3 (group), mw=(wid>>1)&3, np=wid&1
    int mw, np, kw;
    const uint4* wp4;
    float bias0 = 0.0f, bias1 = 0.0f;
    if (layer == 0) {
        mw = wid >> 1; np = wid & 1; kw = 0;
        wp4 = (const uint4*)g_wA0 + ((size_t)(cta * 8 + mw)) * 1024 + lane;
    } else {
        kw = wid >> 3; mw = (wid >> 1) & 3; np = wid & 1;
        wp4 = (const uint4*)g_wAca + ((size_t)(((layer - 1) * 44 + ci) * 8 + mw * 2 + kw)) * 1024 + lane;
        if (kw == 0) {
            const float* cb = ca_b + (size_t)(layer - 1) * G5;
            int s0 = mw * 16 + gr, s1 = s0 + 8;
            if (s0 < 5 * nj) bias0 = cb[(s0 / nj) * 512 + j0 + (s0 % nj)];
            if (s1 < 5 * nj) bias1 = cb[(s1 / nj) * 512 + j0 + (s1 % nj)];
        }
    }
    const int lrow = (np * 2 + ((lane >> 3) >> 1)) * 8 + (lane & 7);
    const uint ldsm_off = bb32 + (uint)(lrow * rs * 2 + ((lane >> 3) & 1) * 16);
    const int kwbase = kw * 512;
    unsigned* myflag = g_flag + ((size_t)layer * 64 + (layer == 0 ? cta : ci)) * 32;
    const unsigned* lowflags = (layer > 0) ? g_flag + ((size_t)(layer - 1) * 64) * 32 : nullptr;
    const unsigned* ownflags = g_flag + ((size_t)layer * 64) * 32;
    const int nc_low = (layer == 1) ? 16 : 44;
    const int nc_own = (layer == 0) ? 16 : 44;

    for (int t = 0; t < Tsz; ++t) {
        const bool active = !(t == 0 && (layer == 0 || kw == 1));

        uint4 w0r, w1r, w2r, w3r;
        if (active) {
            w0r = __ldg(wp4);
            w1r = __ldg(wp4 + 1 * 32);
            w2r = __ldg(wp4 + 2 * 32);
            w3r = __ldg(wp4 + 3 * 32);
        }

        float d[2][4];

        if (layer == 0) {
            if (wid == 0 && t > 0) poll_flags(ownflags, nc_own, (unsigned)t);
            __syncthreads();
            {
                const float* xb = g_xt + ((size_t)t * 2048 + cta * 128) * 32;
                int sl0 = mw * 16 + gr;
                #pragma unroll
                for (int ntp = 0; ntp < 2; ntp++) {
                    int bc = (np * 2 + ntp) * 8 + c0;
                    d[ntp][0] = __ldcg(xb + sl0 * 32 + bc);
                    d[ntp][1] = __ldcg(xb + sl0 * 32 + bc + 1);
                    d[ntp][2] = __ldcg(xb + (sl0 + 8) * 32 + bc);
                    d[ntp][3] = __ldcg(xb + (sl0 + 8) * 32 + bc + 1);
                }
            }
            {
                const uint4 zz = make_uint4(0, 0, 0, 0);
                for (int e = tid; e < 32 * 64; e += NTHR) {
                    int b = e >> 6, c = e & 63;
                    int k8 = c * 8;
                    uint4 vh = (t > 0)
                        ? __ldcg((const uint4*)(g_hh + (((size_t)(t - 1)) * 32 + b) * 512 + k8))
                        : zz;
                    *(uint4*)(Bh + b * rs + k8) = vh;
                }
            }
            __syncthreads();
        } else {
            #pragma unroll
            for (int ntp = 0; ntp < 2; ntp++) {
                d[ntp][0] = bias0; d[ntp][1] = bias0;
                d[ntp][2] = bias1; d[ntp][3] = bias1;
            }
            if (kw == 0) {
                // group A: lower-layer data only
                if (wid == 0) poll_flags(lowflags, nc_low, (unsigned)(t + 1));
                BARX(1);
                for (int e = tid; e < 32 * 64; e += 256) {
                    int b = e >> 6, c = e & 63;
                    int k8 = c * 8;
                    uint4 vh = __ldcg((const uint4*)(
                        g_hh + (((size_t)(layer - 1) * Tsz + t) * 32 + b) * 512 + k8));
                    *(uint4*)(Bh + b * rs + k8) = vh;
                }
                BARX(1);
            } else {
                // group B: own-layer data only
                if (wid == 8 && t > 0) poll_flags(ownflags, nc_own, (unsigned)t);
                BARX(2);
                const uint4 zz = make_uint4(0, 0, 0, 0);
                for (int e = tid - 256; e < 32 * 64; e += 256) {
                    int b = e >> 6, c = e & 63;
                    int k8 = c * 8;
                    uint4 vh = (t > 0)
                        ? __ldcg((const uint4*)(
                              g_hh + (((size_t)layer * Tsz + (t - 1)) * 32 + b) * 512 + k8))
                        : zz;
                    *(uint4*)(Bh + b * rs + 512 + k8) = vh;
                }
                BARX(2);
            }
        }

        // ---- tensor-core GEMM: 1 m-tile x 2 nt x 32 ks per warp ----
        if (active) {
            #pragma unroll
            for (int ks = 0; ks < 32; ks++) {
                uint4 a;
                switch (ks & 3) {
                    case 0: a = w0r; if (ks + 4 < 32) w0r = __ldg(wp4 + (ks + 4) * 32); break;
                    case 1: a = w1r; if (ks + 4 < 32) w1r = __ldg(wp4 + (ks + 4) * 32); break;
                    case 2: a = w2r; if (ks + 4 < 32) w2r = __ldg(wp4 + (ks + 4) * 32); break;
                    default: a = w3r; if (ks + 4 < 32) w3r = __ldg(wp4 + (ks + 4) * 32); break;
                }
                uint b00, b01, b10, b11;
                ldsm_x4(b00, b01, b10, b11,
                        ldsm_off + (uint)((kwbase + ks * 16) * 2));
                mma_f16(d[0], a, b00, b01);
                mma_f16(d[1], a, b10, b11);
            }
        }
        {
            float* pp = part + kw * PSTR;
            #pragma unroll
            for (int ntp = 0; ntp < 2; ntp++) {
                int sl0 = mw * 16 + gr;
                int bc = (np * 2 + ntp) * 8 + c0;
                pp[sl0 * 33 + bc]       = d[ntp][0];
                pp[sl0 * 33 + bc + 1]   = d[ntp][1];
                pp[(sl0 + 8) * 33 + bc]     = d[ntp][2];
                pp[(sl0 + 8) * 33 + bc + 1] = d[ntp][3];
            }
        }
        __syncthreads();

        // ---- activation + state update (c_prev in smem ring) ----
        {
            size_t so = (((size_t)layer * Tsz + t)) * 32;
            float*  cout = g_c  + so * 512;
            ushort* hho  = g_hh + so * 512;
            float* ccur = cring + (t & 1) * 1024;
            float* cprv = cring + ((t & 1) ^ 1) * 1024;
            if (layer == 0) {
                for (int it = tid; it < 1024; it += NTHR) {
                    int b = it >> 5, jj = it & 31;
                    int j = cta * 32 + jj;
                    float i_ = part[(0 * 32 + jj) * 33 + b];
                    float f_ = part[(1 * 32 + jj) * 33 + b];
                    float gg = part[(2 * 32 + jj) * 33 + b];
                    float o_ = part[(3 * 32 + jj) * 33 + b];
                    float cp = (t > 0) ? cprv[it] : 0.0f;
                    float cv = sigf(i_) * tanhef(gg) + sigf(f_) * cp;
                    float hv = sigf(o_) * tanhef(cv);
                    ccur[it] = cv;
                    cout[(size_t)b * 512 + j] = cv;
                    hho[(size_t)b * 512 + j]  = f16of(hv);
                }
            } else {
                const float* clow = g_c + (((size_t)(layer - 1) * Tsz + t) * 32) * 512;
                #define RED(SL, B) (part[(SL) * 33 + (B)] + part[PSTR + (SL) * 33 + (B)])
                for (int it = tid; it < nj * 32; it += NTHR) {
                    int b = it / nj, jj = it - b * nj;
                    int j = j0 + jj;
                    float i_ = RED(0 * nj + jj, b);
                    float fp = RED(1 * nj + jj, b);
                    float fl = RED(2 * nj + jj, b);
                    float u_ = RED(3 * nj + jj, b);
                    float o_ = RED(4 * nj + jj, b);
                    float cp = (t > 0) ? cprv[it] : 0.0f;
                    float cl = __ldcg(clow + (size_t)b * 512 + j);
                    float cv = cp * sigf(fp + 1.0f) + cl * sigf(fl + 1.0f) + tanhef(u_) * sigf(i_);
                    float hv = sigf(o_) * tanhef(cv);
                    ccur[it] = cv;
                    if (layer != 3) cout[(size_t)b * 512 + j] = cv;
                    hho[(size_t)b * 512 + j]  = f16of(hv);
                    if (layer == 3) {
                        out[(size_t)b * Tsz * Hsz + (size_t)t * Hsz + j] = hv;
                        out[BTHn + (size_t)b * Tsz * Hsz + (size_t)t * Hsz + j] = cv;
                        if (t == Tsz - 1) {
                            out[2 * BTHn + (size_t)b * Hsz + j] = hv;
                            out[2 * BTHn + (size_t)Bsz * Hsz + (size_t)b * Hsz + j] = cv;
                        }
                    }
                }
                #undef RED
            }
        }
        __syncthreads();

        // ---- publish completion of step t (own flag line, release store) ----
        if (tid == 0) st_rel(myflag, (unsigned)(t + 1));
    }
}

extern "C" void kernel_launch(void* const* d_in, const int* in_sizes, int n_in,
                              void* d_out, int out_size)
{
    const float* x    = (const float*)d_in[0];
    const float* w_ih = (const float*)d_in[1];
    const float* w_hh = (const float*)d_in[2];
    const float* b_ih = (const float*)d_in[3];
    const float* b_hh = (const float*)d_in[4];
    const float* ca_w = (const float*)d_in[5];
    const float* ca_b = (const float*)d_in[6];
    float* out = (float*)d_out;
    (void)in_sizes; (void)n_in; (void)out_size;

    k_fill<<<296, 256>>>(w_hh, ca_w);

    dim3 g(G4 / 64, (Tsz * Bsz) / 64);
    k_xproj<<<g, 256>>>(x, w_ih, b_ih, b_hh);

    const int smem_bytes = CRING_OFF + 2 * 1024 * 4;  // 108032
    cudaFuncSetAttribute(k_wave, cudaFuncAttributeMaxDynamicSharedMemorySize, smem_bytes);
    k_wave<<<NCTA, NTHR, smem_bytes>>>(ca_b, out);
}